// round 14
// baseline (speedup 1.0000x reference)
#include <cuda_runtime.h>

// PANLoss: block-specialized kernel, 2 smem pair-RMW chains per pixel.
//  sim: t-chain float4 {T2,Ssd,ct,pad} + k-chain float2 {K2,ck} (counts free)
//  dice: register accumulators
// Dynamic smem 55KB -> 4 CTAs/SM. Grid (40+25)x16 = 1040 blocks.
// Inputs: 0 pred_regions f32, 1 regions_gt f32, 2 pred_kernels f32,
//         3 kernels_gt f32, 4 pred_similarities (16,4,640,640) f32,
//         5 text labels i32 [0,8], 6 kernel labels i32 [0,8]
// Output: 5 f32 scalars.

#define HW4    102400
#define NB     16
#define BPBS   40            // sim blocks/batch: 10 iters exact
#define BPBD   25            // dice blocks/batch: 16 iters exact
#define NTH    256
#define NSEG   9
#define NACC   45            // 0-8 T2, 9-17 ct, 18-26 K2, 27-35 ck, 36-44 Ssd
#define EPSF   1e-5f
#define NPXF   409600.0f
#define NBLK   ((BPBS + BPBD) * NB)

// dynamic smem: float4 tp[9*256] (36864 B) + float2 kp[9*256] (18432 B)
#define OFF_KP   36864
#define DYN_SMEM 55296

__device__ float        g_hist[NB * NACC];   // zero at entry (reset in tail)
__device__ float        g_dice[NB * 8];
__device__ unsigned int g_sem;

__device__ __forceinline__ float tanh_fast(float x) {
    float t;
    asm("tanh.approx.f32 %0, %1;" : "=f"(t) : "f"(x));
    return t;
}
__device__ __forceinline__ float4 ldcg4(const float4* p) {
    float4 v;
    asm volatile("ld.global.cg.v4.f32 {%0,%1,%2,%3}, [%4];"
                 : "=f"(v.x), "=f"(v.y), "=f"(v.z), "=f"(v.w) : "l"(p));
    return v;
}
__device__ __forceinline__ int4 ldcg4i(const int4* p) {
    int4 v;
    asm volatile("ld.global.cg.v4.s32 {%0,%1,%2,%3}, [%4];"
                 : "=r"(v.x), "=r"(v.y), "=r"(v.z), "=r"(v.w) : "l"(p));
    return v;
}

extern __shared__ char smem_raw[];

__global__ __launch_bounds__(NTH) void pan_fused(
    const float4* __restrict__ pr, const float4* __restrict__ rg,
    const float4* __restrict__ pk, const float4* __restrict__ kg,
    const float4* __restrict__ sim,
    const int4* __restrict__ tl, const int4* __restrict__ kl,
    float* __restrict__ out)
{
    __shared__ unsigned int s_last;
    const int b   = blockIdx.y;
    const int tid = threadIdx.x;

    if (blockIdx.x < BPBS) {
        // ================= SIM PATH =================
        float4* tp = (float4*)smem_raw;               // {T2, Ssd, ct, pad}
        float2* kp = (float2*)(smem_raw + OFF_KP);    // {K2, ck}
        #pragma unroll
        for (int i = 0; i < NSEG; i++) {
            tp[i * NTH + tid] = make_float4(0.f, 0.f, 0.f, 0.f);
            kp[i * NTH + tid] = make_float2(0.f, 0.f);
        }
        __syncthreads();

        const float4* __restrict__ smb = sim + (size_t)b * 4 * HW4;
        const int4*   __restrict__ tlb = tl + (size_t)b * HW4;
        const int4*   __restrict__ klb = kl + (size_t)b * HW4;

        float4* tpt = &tp[tid];
        float2* kpt = &kp[tid];

        int g = blockIdx.x * NTH + tid;
        const int STR = BPBS * NTH;               // 10240

#define SIM_PROC(s0x, s1x, s2x, s3x, tx, kx) do {                              \
        float s2_ = fmaf((s0x),(s0x), fmaf((s1x),(s1x),                        \
                    fmaf((s2x),(s2x), (s3x)*(s3x))));                          \
        float4 tv_ = tpt[(tx) * NTH];                                          \
        tv_.x += s2_;                                                          \
        tv_.y += ((tx) == (kx)) ? s2_ : 0.0f;                                  \
        tv_.z += 1.0f;                                                         \
        tpt[(tx) * NTH] = tv_;                                                 \
        float2 kv_ = kpt[(kx) * NTH];                                          \
        kv_.x += s2_; kv_.y += 1.0f;                                           \
        kpt[(kx) * NTH] = kv_;                                                 \
    } while (0)

        #pragma unroll 1
        for (int it = 0; it < 5; it++) {
            // batch two groups' 12 loads before the RMW phase
            float4 S0a = ldcg4(smb + g);
            float4 S1a = ldcg4(smb + HW4 + g);
            float4 S2a = ldcg4(smb + 2 * HW4 + g);
            float4 S3a = ldcg4(smb + 3 * HW4 + g);
            int4   Ta  = ldcg4i(tlb + g);
            int4   Ka  = ldcg4i(klb + g);
            int g2 = g + STR;
            float4 S0b = ldcg4(smb + g2);
            float4 S1b = ldcg4(smb + HW4 + g2);
            float4 S2b = ldcg4(smb + 2 * HW4 + g2);
            float4 S3b = ldcg4(smb + 3 * HW4 + g2);
            int4   Tb  = ldcg4i(tlb + g2);
            int4   Kb  = ldcg4i(klb + g2);

            SIM_PROC(S0a.x, S1a.x, S2a.x, S3a.x, Ta.x, Ka.x);
            SIM_PROC(S0a.y, S1a.y, S2a.y, S3a.y, Ta.y, Ka.y);
            SIM_PROC(S0a.z, S1a.z, S2a.z, S3a.z, Ta.z, Ka.z);
            SIM_PROC(S0a.w, S1a.w, S2a.w, S3a.w, Ta.w, Ka.w);
            SIM_PROC(S0b.x, S1b.x, S2b.x, S3b.x, Tb.x, Kb.x);
            SIM_PROC(S0b.y, S1b.y, S2b.y, S3b.y, Tb.y, Kb.y);
            SIM_PROC(S0b.z, S1b.z, S2b.z, S3b.z, Tb.z, Kb.z);
            SIM_PROC(S0b.w, S1b.w, S2b.w, S3b.w, Tb.w, Kb.w);
            g += 2 * STR;
        }
#undef SIM_PROC
        __syncthreads();

        // ---- block-reduce private bins, flush ----
        #pragma unroll
        for (int s = NTH / 2; s >= 32; s >>= 1) {
            if (tid < s) {
                #pragma unroll
                for (int i = 0; i < NSEG; i++) {
                    float4 a0 = tp[i * NTH + tid], b0 = tp[i * NTH + tid + s];
                    a0.x += b0.x; a0.y += b0.y; a0.z += b0.z;
                    tp[i * NTH + tid] = a0;
                    float2 c0 = kp[i * NTH + tid], d0 = kp[i * NTH + tid + s];
                    c0.x += d0.x; c0.y += d0.y;
                    kp[i * NTH + tid] = c0;
                }
            }
            __syncthreads();
        }
        if (tid < 32) {
            #pragma unroll
            for (int i = 0; i < NSEG; i++) {
                float4 v = tp[i * NTH + tid];
                float2 w = kp[i * NTH + tid];
                #pragma unroll
                for (int o = 16; o; o >>= 1) {
                    v.x += __shfl_down_sync(0xffffffffu, v.x, o);
                    v.y += __shfl_down_sync(0xffffffffu, v.y, o);
                    v.z += __shfl_down_sync(0xffffffffu, v.z, o);
                    w.x += __shfl_down_sync(0xffffffffu, w.x, o);
                    w.y += __shfl_down_sync(0xffffffffu, w.y, o);
                }
                if (tid == 0) {
                    atomicAdd(&g_hist[b * NACC + i],      v.x);   // T2
                    atomicAdd(&g_hist[b * NACC + 36 + i], v.y);   // Ssd
                    atomicAdd(&g_hist[b * NACC + 9 + i],  v.z);   // ct
                    atomicAdd(&g_hist[b * NACC + 18 + i], w.x);   // K2
                    atomicAdd(&g_hist[b * NACC + 27 + i], w.y);   // ck
                }
            }
        }
    } else {
        // ================= DICE PATH =================
        const int dbx = blockIdx.x - BPBS;
        const float4* __restrict__ prb = pr + (size_t)b * HW4;
        const float4* __restrict__ rgb = rg + (size_t)b * HW4;
        const float4* __restrict__ pkb = pk + (size_t)b * HW4;
        const float4* __restrict__ kgb = kg + (size_t)b * HW4;

        float St_r = 0.f, St2_r = 0.f, Sgt_r = 0.f, Sg_r = 0.f;
        float St_k = 0.f, St2_k = 0.f, Sgt_k = 0.f, Sg_k = 0.f;

        int g = dbx * NTH + tid;
        const int STR = BPBD * NTH;               // 6400

#define DICE_PROC(ax, gx, cx, dx) do {                                         \
        float t1_ = tanh_fast(0.5f * (ax));                                    \
        St_r  += t1_;                                                          \
        St2_r  = fmaf(t1_, t1_, St2_r);                                        \
        Sgt_r  = fmaf(t1_, (gx), Sgt_r);                                       \
        Sg_r  += (gx);                                                         \
        float t2_ = tanh_fast(0.5f * (cx));                                    \
        St_k  += t2_;                                                          \
        St2_k  = fmaf(t2_, t2_, St2_k);                                        \
        Sgt_k  = fmaf(t2_, (dx), Sgt_k);                                       \
        Sg_k  += (dx);                                                         \
    } while (0)

        #pragma unroll 1
        for (int it = 0; it < 8; it++) {
            float4 Aa = ldcg4(prb + g);
            float4 Ga = ldcg4(rgb + g);
            float4 Ca = ldcg4(pkb + g);
            float4 Da = ldcg4(kgb + g);
            int g2 = g + STR;
            float4 Ab = ldcg4(prb + g2);
            float4 Gb = ldcg4(rgb + g2);
            float4 Cb = ldcg4(pkb + g2);
            float4 Db = ldcg4(kgb + g2);

            DICE_PROC(Aa.x, Ga.x, Ca.x, Da.x);
            DICE_PROC(Aa.y, Ga.y, Ca.y, Da.y);
            DICE_PROC(Aa.z, Ga.z, Ca.z, Da.z);
            DICE_PROC(Aa.w, Ga.w, Ca.w, Da.w);
            DICE_PROC(Ab.x, Gb.x, Cb.x, Db.x);
            DICE_PROC(Ab.y, Gb.y, Cb.y, Db.y);
            DICE_PROC(Ab.z, Gb.z, Cb.z, Db.z);
            DICE_PROC(Ab.w, Gb.w, Cb.w, Db.w);
            g += 2 * STR;
        }
#undef DICE_PROC

        #pragma unroll
        for (int o = 16; o; o >>= 1) {
            St_r  += __shfl_down_sync(0xffffffffu, St_r,  o);
            St2_r += __shfl_down_sync(0xffffffffu, St2_r, o);
            Sgt_r += __shfl_down_sync(0xffffffffu, Sgt_r, o);
            Sg_r  += __shfl_down_sync(0xffffffffu, Sg_r,  o);
            St_k  += __shfl_down_sync(0xffffffffu, St_k,  o);
            St2_k += __shfl_down_sync(0xffffffffu, St2_k, o);
            Sgt_k += __shfl_down_sync(0xffffffffu, Sgt_k, o);
            Sg_k  += __shfl_down_sync(0xffffffffu, Sg_k,  o);
        }
        if ((tid & 31) == 0) {
            atomicAdd(&g_dice[b*8+0], St_r);  atomicAdd(&g_dice[b*8+1], St2_r);
            atomicAdd(&g_dice[b*8+2], Sgt_r); atomicAdd(&g_dice[b*8+3], Sg_r);
            atomicAdd(&g_dice[b*8+4], St_k);  atomicAdd(&g_dice[b*8+5], St2_k);
            atomicAdd(&g_dice[b*8+6], Sgt_k); atomicAdd(&g_dice[b*8+7], Sg_k);
        }
    }

    __threadfence();
    __syncthreads();
    if (tid == 0)
        s_last = (atomicAdd(&g_sem, 1u) == (unsigned)(NBLK - 1)) ? 1u : 0u;
    __syncthreads();
    if (!s_last) return;

    // ---------------- finalize (last block only) ----------------
    __threadfence();

    float lr = 0.f, lk = 0.f, lagg = 0.f, ldis = 0.f;
    if (tid < NB) {
        float T2[NSEG], ct[NSEG], K2[NSEG], ck[NSEG], Ssd[NSEG], a[8];
        #pragma unroll
        for (int i = 0; i < NSEG; i++) {
            T2[i]  = g_hist[tid * NACC + i];
            ct[i]  = g_hist[tid * NACC + 9 + i];
            K2[i]  = g_hist[tid * NACC + 18 + i];
            ck[i]  = g_hist[tid * NACC + 27 + i];
            Ssd[i] = g_hist[tid * NACC + 36 + i];
        }

        float St  = g_dice[tid*8+0], St2 = g_dice[tid*8+1];
        float Sgt = g_dice[tid*8+2], Sg  = g_dice[tid*8+3];
        float I = 0.5f * (Sgt + Sg);
        float P = 0.25f * (NPXF + 2.f * St + St2);
        lr = 1.0f - (2.0f * I + EPSF) / ((P + EPSF) + (Sg + EPSF));

        St  = g_dice[tid*8+4]; St2 = g_dice[tid*8+5];
        Sgt = g_dice[tid*8+6]; Sg  = g_dice[tid*8+7];
        I = 0.5f * (Sgt + Sg);
        P = 0.25f * (NPXF + 2.f * St + St2);
        lk = 1.0f - (2.0f * I + EPSF) / ((P + EPSF) + (Sg + EPSF));

        #pragma unroll 1
        for (int i = 1; i < NSEG; i++) {
            float inv = 1.0f / (ck[i] + 1.0f);
            float n2  = T2[i] - (2.0f * inv - inv * inv) * Ssd[i]
                        + inv * inv * (K2[i] - Ssd[i]);
            float nrm = sqrtf(fmaxf(n2, 0.0f));
            float d   = nrm - 0.5f;                    // SIGMA_AGG (no clamp)
            lagg += logf(d * d + 1.0f) / (ct[i] + 1.0f);
            float c1 = ck[i] + 0.001f;
            a[i - 1] = K2[i] / (c1 * c1);
        }
        #pragma unroll 1
        for (int i = 0; i < 8; i++)
            #pragma unroll 1
            for (int j = i + 1; j < 8; j++) {
                float pr_ = 3.0f - sqrtf(a[i] + a[j]); // SIGMA_DIS
                ldis += logf(pr_ * pr_ + 1.0f);
            }
        ldis *= (1.0f / 56.0f);
    }

    if (tid < 32) {
        #pragma unroll
        for (int o = 16; o; o >>= 1) {
            lr   += __shfl_down_sync(0xffffffffu, lr,   o);
            lk   += __shfl_down_sync(0xffffffffu, lk,   o);
            lagg += __shfl_down_sync(0xffffffffu, lagg, o);
            ldis += __shfl_down_sync(0xffffffffu, ldis, o);
        }
        if (tid == 0) {
            out[0] = lr + 0.5f * lk + 0.25f * (lagg + ldis);  // ALPHA, BETA
            out[1] = lr;
            out[2] = lk;
            out[3] = lagg;
            out[4] = ldis;
        }
    }
    __syncthreads();

    // reset scratch for next graph replay
    for (int i = tid; i < NB * NACC; i += NTH) g_hist[i] = 0.f;
    for (int i = tid; i < NB * 8;    i += NTH) g_dice[i] = 0.f;
    __threadfence();
    __syncthreads();
    if (tid == 0) g_sem = 0u;
}

extern "C" void kernel_launch(void* const* d_in, const int* in_sizes, int n_in,
                              void* d_out, int out_size) {
    (void)in_sizes; (void)n_in; (void)out_size;
    cudaFuncSetAttribute(pan_fused,
                         cudaFuncAttributeMaxDynamicSharedMemorySize, DYN_SMEM);
    dim3 grid(BPBS + BPBD, NB);
    pan_fused<<<grid, NTH, DYN_SMEM>>>(
        (const float4*)d_in[0], (const float4*)d_in[1],
        (const float4*)d_in[2], (const float4*)d_in[3],
        (const float4*)d_in[4],
        (const int4*)d_in[5],  (const int4*)d_in[6],
        (float*)d_out);
}

// round 15
// speedup vs baseline: 1.1772x; 1.1772x over previous
#include <cuda_runtime.h>

// PANLoss: block-specialized fused kernel (best-known configuration, R6).
//  - "sim" blocks: 6 streams (4 sim planes + 2 label maps) -> private smem bins
//  - "dice" blocks: 4 streams (pred/gt x2) -> register accumulators only
// Inputs: 0 pred_regions f32, 1 regions_gt f32, 2 pred_kernels f32,
//         3 kernels_gt f32, 4 pred_similarities (16,4,640,640) f32,
//         5 text labels i32 [0,8], 6 kernel labels i32 [0,8]
// Output: 5 f32 scalars.

#define HW4    102400
#define NB     16
#define BPBS   40            // sim blocks/batch: 102400/(40*256)=10 iters exact
#define BPBD   25            // dice blocks/batch: 16 iters exact
#define NTH    256
#define NSEG   9
#define NACC   45            // 0-8 T2, 9-17 ct, 18-26 K2, 27-35 ck, 36-44 Ssd
#define EPSF   1e-5f
#define NPXF   409600.0f
#define NBLK   ((BPBS + BPBD) * NB)

__device__ float        g_hist[NB * NACC];   // zero at entry (reset in tail)
__device__ float        g_dice[NB * 8];
__device__ unsigned int g_sem;

__device__ __forceinline__ float tanh_fast(float x) {
    float t;
    asm("tanh.approx.f32 %0, %1;" : "=f"(t) : "f"(x));
    return t;
}
__device__ __forceinline__ float4 ldcg4(const float4* p) {
    float4 v;
    asm volatile("ld.global.cg.v4.f32 {%0,%1,%2,%3}, [%4];"
                 : "=f"(v.x), "=f"(v.y), "=f"(v.z), "=f"(v.w) : "l"(p));
    return v;
}
__device__ __forceinline__ int4 ldcg4i(const int4* p) {
    int4 v;
    asm volatile("ld.global.cg.v4.s32 {%0,%1,%2,%3}, [%4];"
                 : "=r"(v.x), "=r"(v.y), "=r"(v.z), "=r"(v.w) : "l"(p));
    return v;
}

__global__ __launch_bounds__(NTH) void pan_fused(
    const float4* __restrict__ pr, const float4* __restrict__ rg,
    const float4* __restrict__ pk, const float4* __restrict__ kg,
    const float4* __restrict__ sim,
    const int4* __restrict__ tl, const int4* __restrict__ kl,
    float* __restrict__ out)
{
    __shared__ float2 sh2[18 * NTH];   // [0..9) t-pairs {s2,cnt}, [9..18) k-pairs
    __shared__ float  shd[NSEG * NTH]; // diag s2
    __shared__ unsigned int s_last;
    const int b   = blockIdx.y;
    const int tid = threadIdx.x;

    if (blockIdx.x < BPBS) {
        // ================= SIM PATH =================
        #pragma unroll
        for (int i = 0; i < 18; i++) sh2[i * NTH + tid] = make_float2(0.f, 0.f);
        #pragma unroll
        for (int i = 0; i < NSEG; i++) shd[i * NTH + tid] = 0.f;
        __syncthreads();

        const float4* __restrict__ smb = sim + (size_t)b * 4 * HW4;
        const int4*   __restrict__ tlb = tl + (size_t)b * HW4;
        const int4*   __restrict__ klb = kl + (size_t)b * HW4;

        float2* sht = &sh2[tid];
        float2* shk = &sh2[9 * NTH + tid];
        float*  shD = &shd[tid];

        int g = blockIdx.x * NTH + tid;
        const int STR = BPBS * NTH;               // 10240

#define SIM_PROC(s0x, s1x, s2x, s3x, tx, kx) do {                              \
        float s2_ = fmaf((s0x),(s0x), fmaf((s1x),(s1x),                        \
                    fmaf((s2x),(s2x), (s3x)*(s3x))));                          \
        float2 tv_ = sht[(tx) * NTH];                                          \
        tv_.x += s2_; tv_.y += 1.0f;                                           \
        sht[(tx) * NTH] = tv_;                                                 \
        float2 kv_ = shk[(kx) * NTH];                                          \
        kv_.x += s2_; kv_.y += 1.0f;                                           \
        shk[(kx) * NTH] = kv_;                                                 \
        shD[(tx) * NTH] += ((tx) == (kx)) ? s2_ : 0.0f;                        \
    } while (0)

        #pragma unroll 1
        for (int it = 0; it < 5; it++) {
            // batch all 12 loads of two groups before any STS
            float4 S0a = ldcg4(smb + g);
            float4 S1a = ldcg4(smb + HW4 + g);
            float4 S2a = ldcg4(smb + 2 * HW4 + g);
            float4 S3a = ldcg4(smb + 3 * HW4 + g);
            int4   Ta  = ldcg4i(tlb + g);
            int4   Ka  = ldcg4i(klb + g);
            int g2 = g + STR;
            float4 S0b = ldcg4(smb + g2);
            float4 S1b = ldcg4(smb + HW4 + g2);
            float4 S2b = ldcg4(smb + 2 * HW4 + g2);
            float4 S3b = ldcg4(smb + 3 * HW4 + g2);
            int4   Tb  = ldcg4i(tlb + g2);
            int4   Kb  = ldcg4i(klb + g2);

            SIM_PROC(S0a.x, S1a.x, S2a.x, S3a.x, Ta.x, Ka.x);
            SIM_PROC(S0a.y, S1a.y, S2a.y, S3a.y, Ta.y, Ka.y);
            SIM_PROC(S0a.z, S1a.z, S2a.z, S3a.z, Ta.z, Ka.z);
            SIM_PROC(S0a.w, S1a.w, S2a.w, S3a.w, Ta.w, Ka.w);
            SIM_PROC(S0b.x, S1b.x, S2b.x, S3b.x, Tb.x, Kb.x);
            SIM_PROC(S0b.y, S1b.y, S2b.y, S3b.y, Tb.y, Kb.y);
            SIM_PROC(S0b.z, S1b.z, S2b.z, S3b.z, Tb.z, Kb.z);
            SIM_PROC(S0b.w, S1b.w, S2b.w, S3b.w, Tb.w, Kb.w);
            g += 2 * STR;
        }
#undef SIM_PROC
        __syncthreads();

        // block-reduce private bins, flush
        #pragma unroll
        for (int s = NTH / 2; s >= 32; s >>= 1) {
            if (tid < s) {
                #pragma unroll
                for (int i = 0; i < 18; i++) {
                    float2 a0 = sh2[i * NTH + tid], b0 = sh2[i * NTH + tid + s];
                    a0.x += b0.x; a0.y += b0.y;
                    sh2[i * NTH + tid] = a0;
                }
                #pragma unroll
                for (int i = 0; i < NSEG; i++)
                    shd[i * NTH + tid] += shd[i * NTH + tid + s];
            }
            __syncthreads();
        }
        if (tid < 32) {
            #pragma unroll
            for (int i = 0; i < 18; i++) {
                float2 v = sh2[i * NTH + tid];
                #pragma unroll
                for (int o = 16; o; o >>= 1) {
                    v.x += __shfl_down_sync(0xffffffffu, v.x, o);
                    v.y += __shfl_down_sync(0xffffffffu, v.y, o);
                }
                if (tid == 0) {
                    int base = (i < 9) ? 0 : 9;
                    int lbl  = (i < 9) ? i : i - 9;
                    atomicAdd(&g_hist[b * NACC + base * 2 + lbl], v.x);
                    atomicAdd(&g_hist[b * NACC + base * 2 + 9 + lbl], v.y);
                }
            }
            #pragma unroll
            for (int i = 0; i < NSEG; i++) {
                float v = shd[i * NTH + tid];
                #pragma unroll
                for (int o = 16; o; o >>= 1)
                    v += __shfl_down_sync(0xffffffffu, v, o);
                if (tid == 0) atomicAdd(&g_hist[b * NACC + 36 + i], v);
            }
        }
    } else {
        // ================= DICE PATH =================
        const int dbx = blockIdx.x - BPBS;
        const float4* __restrict__ prb = pr + (size_t)b * HW4;
        const float4* __restrict__ rgb = rg + (size_t)b * HW4;
        const float4* __restrict__ pkb = pk + (size_t)b * HW4;
        const float4* __restrict__ kgb = kg + (size_t)b * HW4;

        float St_r = 0.f, St2_r = 0.f, Sgt_r = 0.f, Sg_r = 0.f;
        float St_k = 0.f, St2_k = 0.f, Sgt_k = 0.f, Sg_k = 0.f;

        int g = dbx * NTH + tid;
        const int STR = BPBD * NTH;               // 6400

#define DICE_PROC(ax, gx, cx, dx) do {                                         \
        float t1_ = tanh_fast(0.5f * (ax));                                    \
        St_r  += t1_;                                                          \
        St2_r  = fmaf(t1_, t1_, St2_r);                                        \
        Sgt_r  = fmaf(t1_, (gx), Sgt_r);                                       \
        Sg_r  += (gx);                                                         \
        float t2_ = tanh_fast(0.5f * (cx));                                    \
        St_k  += t2_;                                                          \
        St2_k  = fmaf(t2_, t2_, St2_k);                                        \
        Sgt_k  = fmaf(t2_, (dx), Sgt_k);                                       \
        Sg_k  += (dx);                                                         \
    } while (0)

        #pragma unroll 1
        for (int it = 0; it < 8; it++) {
            float4 Aa = ldcg4(prb + g);
            float4 Ga = ldcg4(rgb + g);
            float4 Ca = ldcg4(pkb + g);
            float4 Da = ldcg4(kgb + g);
            int g2 = g + STR;
            float4 Ab = ldcg4(prb + g2);
            float4 Gb = ldcg4(rgb + g2);
            float4 Cb = ldcg4(pkb + g2);
            float4 Db = ldcg4(kgb + g2);

            DICE_PROC(Aa.x, Ga.x, Ca.x, Da.x);
            DICE_PROC(Aa.y, Ga.y, Ca.y, Da.y);
            DICE_PROC(Aa.z, Ga.z, Ca.z, Da.z);
            DICE_PROC(Aa.w, Ga.w, Ca.w, Da.w);
            DICE_PROC(Ab.x, Gb.x, Cb.x, Db.x);
            DICE_PROC(Ab.y, Gb.y, Cb.y, Db.y);
            DICE_PROC(Ab.z, Gb.z, Cb.z, Db.z);
            DICE_PROC(Ab.w, Gb.w, Cb.w, Db.w);
            g += 2 * STR;
        }
#undef DICE_PROC

        #pragma unroll
        for (int o = 16; o; o >>= 1) {
            St_r  += __shfl_down_sync(0xffffffffu, St_r,  o);
            St2_r += __shfl_down_sync(0xffffffffu, St2_r, o);
            Sgt_r += __shfl_down_sync(0xffffffffu, Sgt_r, o);
            Sg_r  += __shfl_down_sync(0xffffffffu, Sg_r,  o);
            St_k  += __shfl_down_sync(0xffffffffu, St_k,  o);
            St2_k += __shfl_down_sync(0xffffffffu, St2_k, o);
            Sgt_k += __shfl_down_sync(0xffffffffu, Sgt_k, o);
            Sg_k  += __shfl_down_sync(0xffffffffu, Sg_k,  o);
        }
        if ((tid & 31) == 0) {
            atomicAdd(&g_dice[b*8+0], St_r);  atomicAdd(&g_dice[b*8+1], St2_r);
            atomicAdd(&g_dice[b*8+2], Sgt_r); atomicAdd(&g_dice[b*8+3], Sg_r);
            atomicAdd(&g_dice[b*8+4], St_k);  atomicAdd(&g_dice[b*8+5], St2_k);
            atomicAdd(&g_dice[b*8+6], Sgt_k); atomicAdd(&g_dice[b*8+7], Sg_k);
        }
    }

    __threadfence();
    __syncthreads();
    if (tid == 0)
        s_last = (atomicAdd(&g_sem, 1u) == (unsigned)(NBLK - 1)) ? 1u : 0u;
    __syncthreads();
    if (!s_last) return;

    // ---------------- finalize (last block only) ----------------
    __threadfence();

    float lr = 0.f, lk = 0.f, lagg = 0.f, ldis = 0.f;
    if (tid < NB) {
        float T2[NSEG], ct[NSEG], K2[NSEG], ck[NSEG], Ssd[NSEG], a[8];
        #pragma unroll
        for (int i = 0; i < NSEG; i++) {
            T2[i]  = g_hist[tid * NACC + i];
            ct[i]  = g_hist[tid * NACC + 9 + i];
            K2[i]  = g_hist[tid * NACC + 18 + i];
            ck[i]  = g_hist[tid * NACC + 27 + i];
            Ssd[i] = g_hist[tid * NACC + 36 + i];
        }

        float St  = g_dice[tid*8+0], St2 = g_dice[tid*8+1];
        float Sgt = g_dice[tid*8+2], Sg  = g_dice[tid*8+3];
        float I = 0.5f * (Sgt + Sg);
        float P = 0.25f * (NPXF + 2.f * St + St2);
        lr = 1.0f - (2.0f * I + EPSF) / ((P + EPSF) + (Sg + EPSF));

        St  = g_dice[tid*8+4]; St2 = g_dice[tid*8+5];
        Sgt = g_dice[tid*8+6]; Sg  = g_dice[tid*8+7];
        I = 0.5f * (Sgt + Sg);
        P = 0.25f * (NPXF + 2.f * St + St2);
        lk = 1.0f - (2.0f * I + EPSF) / ((P + EPSF) + (Sg + EPSF));

        #pragma unroll 1
        for (int i = 1; i < NSEG; i++) {
            float inv = 1.0f / (ck[i] + 1.0f);
            float n2  = T2[i] - (2.0f * inv - inv * inv) * Ssd[i]
                        + inv * inv * (K2[i] - Ssd[i]);
            float nrm = sqrtf(fmaxf(n2, 0.0f));
            float d   = nrm - 0.5f;                    // SIGMA_AGG (no clamp)
            lagg += logf(d * d + 1.0f) / (ct[i] + 1.0f);
            float c1 = ck[i] + 0.001f;
            a[i - 1] = K2[i] / (c1 * c1);
        }
        #pragma unroll 1
        for (int i = 0; i < 8; i++)
            #pragma unroll 1
            for (int j = i + 1; j < 8; j++) {
                float pr_ = 3.0f - sqrtf(a[i] + a[j]); // SIGMA_DIS
                ldis += logf(pr_ * pr_ + 1.0f);
            }
        ldis *= (1.0f / 56.0f);
    }

    if (tid < 32) {
        #pragma unroll
        for (int o = 16; o; o >>= 1) {
            lr   += __shfl_down_sync(0xffffffffu, lr,   o);
            lk   += __shfl_down_sync(0xffffffffu, lk,   o);
            lagg += __shfl_down_sync(0xffffffffu, lagg, o);
            ldis += __shfl_down_sync(0xffffffffu, ldis, o);
        }
        if (tid == 0) {
            out[0] = lr + 0.5f * lk + 0.25f * (lagg + ldis);  // ALPHA, BETA
            out[1] = lr;
            out[2] = lk;
            out[3] = lagg;
            out[4] = ldis;
        }
    }
    __syncthreads();

    // reset scratch for next graph replay
    for (int i = tid; i < NB * NACC; i += NTH) g_hist[i] = 0.f;
    for (int i = tid; i < NB * 8;    i += NTH) g_dice[i] = 0.f;
    __threadfence();
    __syncthreads();
    if (tid == 0) g_sem = 0u;
}

extern "C" void kernel_launch(void* const* d_in, const int* in_sizes, int n_in,
                              void* d_out, int out_size) {
    (void)in_sizes; (void)n_in; (void)out_size;
    dim3 grid(BPBS + BPBD, NB);
    pan_fused<<<grid, NTH>>>(
        (const float4*)d_in[0], (const float4*)d_in[1],
        (const float4*)d_in[2], (const float4*)d_in[3],
        (const float4*)d_in[4],
        (const int4*)d_in[5],  (const int4*)d_in[6],
        (float*)d_out);
}

// round 16
// speedup vs baseline: 1.2711x; 1.0798x over previous
#include <cuda_runtime.h>

// PANLoss: R6 hot-loop in a single-wave persistent grid.
// Grid 37x16 = 592 blocks = exactly 4 CTAs/SM x 148 SMs (one wave, no tail).
// Per batch: 22 sim blocks (6 streams -> private smem bins), 15 dice blocks
// (4 streams -> register accumulators). Inner bodies identical to R6.
// Inputs: 0 pred_regions f32, 1 regions_gt f32, 2 pred_kernels f32,
//         3 kernels_gt f32, 4 pred_similarities (16,4,640,640) f32,
//         5 text labels i32 [0,8], 6 kernel labels i32 [0,8]
// Output: 5 f32 scalars.

#define HW4    102400
#define NB     16
#define BPBS   22            // sim blocks/batch (strided, ~18.2 iters)
#define BPBD   15            // dice blocks/batch (strided, ~26.7 iters)
#define NTH    256
#define NSEG   9
#define NACC   45            // 0-8 T2, 9-17 ct, 18-26 K2, 27-35 ck, 36-44 Ssd
#define EPSF   1e-5f
#define NPXF   409600.0f
#define NBLK   ((BPBS + BPBD) * NB)   // 592

__device__ float        g_hist[NB * NACC];   // zero at entry (reset in tail)
__device__ float        g_dice[NB * 8];
__device__ unsigned int g_sem;

__device__ __forceinline__ float tanh_fast(float x) {
    float t;
    asm("tanh.approx.f32 %0, %1;" : "=f"(t) : "f"(x));
    return t;
}
__device__ __forceinline__ float4 ldcg4(const float4* p) {
    float4 v;
    asm volatile("ld.global.cg.v4.f32 {%0,%1,%2,%3}, [%4];"
                 : "=f"(v.x), "=f"(v.y), "=f"(v.z), "=f"(v.w) : "l"(p));
    return v;
}
__device__ __forceinline__ int4 ldcg4i(const int4* p) {
    int4 v;
    asm volatile("ld.global.cg.v4.s32 {%0,%1,%2,%3}, [%4];"
                 : "=r"(v.x), "=r"(v.y), "=r"(v.z), "=r"(v.w) : "l"(p));
    return v;
}

__global__ __launch_bounds__(NTH) void pan_fused(
    const float4* __restrict__ pr, const float4* __restrict__ rg,
    const float4* __restrict__ pk, const float4* __restrict__ kg,
    const float4* __restrict__ sim,
    const int4* __restrict__ tl, const int4* __restrict__ kl,
    float* __restrict__ out)
{
    __shared__ float2 sh2[18 * NTH];   // [0..9) t-pairs {s2,cnt}, [9..18) k-pairs
    __shared__ float  shd[NSEG * NTH]; // diag s2
    __shared__ unsigned int s_last;
    const int b   = blockIdx.y;
    const int tid = threadIdx.x;

    if (blockIdx.x < BPBS) {
        // ================= SIM PATH =================
        #pragma unroll
        for (int i = 0; i < 18; i++) sh2[i * NTH + tid] = make_float2(0.f, 0.f);
        #pragma unroll
        for (int i = 0; i < NSEG; i++) shd[i * NTH + tid] = 0.f;
        __syncthreads();

        const float4* __restrict__ smb = sim + (size_t)b * 4 * HW4;
        const int4*   __restrict__ tlb = tl + (size_t)b * HW4;
        const int4*   __restrict__ klb = kl + (size_t)b * HW4;

        float2* sht = &sh2[tid];
        float2* shk = &sh2[9 * NTH + tid];
        float*  shD = &shd[tid];

        int g = blockIdx.x * NTH + tid;
        const int STR = BPBS * NTH;               // 5632

#define SIM_PROC(s0x, s1x, s2x, s3x, tx, kx) do {                              \
        float s2_ = fmaf((s0x),(s0x), fmaf((s1x),(s1x),                        \
                    fmaf((s2x),(s2x), (s3x)*(s3x))));                          \
        float2 tv_ = sht[(tx) * NTH];                                          \
        tv_.x += s2_; tv_.y += 1.0f;                                           \
        sht[(tx) * NTH] = tv_;                                                 \
        float2 kv_ = shk[(kx) * NTH];                                          \
        kv_.x += s2_; kv_.y += 1.0f;                                           \
        shk[(kx) * NTH] = kv_;                                                 \
        shD[(tx) * NTH] += ((tx) == (kx)) ? s2_ : 0.0f;                        \
    } while (0)

        // pair iterations: both groups in range
        while (g + STR < HW4) {
            float4 S0a = ldcg4(smb + g);
            float4 S1a = ldcg4(smb + HW4 + g);
            float4 S2a = ldcg4(smb + 2 * HW4 + g);
            float4 S3a = ldcg4(smb + 3 * HW4 + g);
            int4   Ta  = ldcg4i(tlb + g);
            int4   Ka  = ldcg4i(klb + g);
            int g2 = g + STR;
            float4 S0b = ldcg4(smb + g2);
            float4 S1b = ldcg4(smb + HW4 + g2);
            float4 S2b = ldcg4(smb + 2 * HW4 + g2);
            float4 S3b = ldcg4(smb + 3 * HW4 + g2);
            int4   Tb  = ldcg4i(tlb + g2);
            int4   Kb  = ldcg4i(klb + g2);

            SIM_PROC(S0a.x, S1a.x, S2a.x, S3a.x, Ta.x, Ka.x);
            SIM_PROC(S0a.y, S1a.y, S2a.y, S3a.y, Ta.y, Ka.y);
            SIM_PROC(S0a.z, S1a.z, S2a.z, S3a.z, Ta.z, Ka.z);
            SIM_PROC(S0a.w, S1a.w, S2a.w, S3a.w, Ta.w, Ka.w);
            SIM_PROC(S0b.x, S1b.x, S2b.x, S3b.x, Tb.x, Kb.x);
            SIM_PROC(S0b.y, S1b.y, S2b.y, S3b.y, Tb.y, Kb.y);
            SIM_PROC(S0b.z, S1b.z, S2b.z, S3b.z, Tb.z, Kb.z);
            SIM_PROC(S0b.w, S1b.w, S2b.w, S3b.w, Tb.w, Kb.w);
            g += 2 * STR;
        }
        // single-group tail
        if (g < HW4) {
            float4 S0 = ldcg4(smb + g);
            float4 S1 = ldcg4(smb + HW4 + g);
            float4 S2 = ldcg4(smb + 2 * HW4 + g);
            float4 S3 = ldcg4(smb + 3 * HW4 + g);
            int4   T  = ldcg4i(tlb + g);
            int4   K  = ldcg4i(klb + g);
            SIM_PROC(S0.x, S1.x, S2.x, S3.x, T.x, K.x);
            SIM_PROC(S0.y, S1.y, S2.y, S3.y, T.y, K.y);
            SIM_PROC(S0.z, S1.z, S2.z, S3.z, T.z, K.z);
            SIM_PROC(S0.w, S1.w, S2.w, S3.w, T.w, K.w);
        }
#undef SIM_PROC
        __syncthreads();

        // block-reduce private bins, flush
        #pragma unroll
        for (int s = NTH / 2; s >= 32; s >>= 1) {
            if (tid < s) {
                #pragma unroll
                for (int i = 0; i < 18; i++) {
                    float2 a0 = sh2[i * NTH + tid], b0 = sh2[i * NTH + tid + s];
                    a0.x += b0.x; a0.y += b0.y;
                    sh2[i * NTH + tid] = a0;
                }
                #pragma unroll
                for (int i = 0; i < NSEG; i++)
                    shd[i * NTH + tid] += shd[i * NTH + tid + s];
            }
            __syncthreads();
        }
        if (tid < 32) {
            #pragma unroll
            for (int i = 0; i < 18; i++) {
                float2 v = sh2[i * NTH + tid];
                #pragma unroll
                for (int o = 16; o; o >>= 1) {
                    v.x += __shfl_down_sync(0xffffffffu, v.x, o);
                    v.y += __shfl_down_sync(0xffffffffu, v.y, o);
                }
                if (tid == 0) {
                    int base = (i < 9) ? 0 : 9;
                    int lbl  = (i < 9) ? i : i - 9;
                    atomicAdd(&g_hist[b * NACC + base * 2 + lbl], v.x);
                    atomicAdd(&g_hist[b * NACC + base * 2 + 9 + lbl], v.y);
                }
            }
            #pragma unroll
            for (int i = 0; i < NSEG; i++) {
                float v = shd[i * NTH + tid];
                #pragma unroll
                for (int o = 16; o; o >>= 1)
                    v += __shfl_down_sync(0xffffffffu, v, o);
                if (tid == 0) atomicAdd(&g_hist[b * NACC + 36 + i], v);
            }
        }
    } else {
        // ================= DICE PATH =================
        const int dbx = blockIdx.x - BPBS;
        const float4* __restrict__ prb = pr + (size_t)b * HW4;
        const float4* __restrict__ rgb = rg + (size_t)b * HW4;
        const float4* __restrict__ pkb = pk + (size_t)b * HW4;
        const float4* __restrict__ kgb = kg + (size_t)b * HW4;

        float St_r = 0.f, St2_r = 0.f, Sgt_r = 0.f, Sg_r = 0.f;
        float St_k = 0.f, St2_k = 0.f, Sgt_k = 0.f, Sg_k = 0.f;

        int g = dbx * NTH + tid;
        const int STR = BPBD * NTH;               // 3840

#define DICE_PROC(ax, gx, cx, dx) do {                                         \
        float t1_ = tanh_fast(0.5f * (ax));                                    \
        St_r  += t1_;                                                          \
        St2_r  = fmaf(t1_, t1_, St2_r);                                        \
        Sgt_r  = fmaf(t1_, (gx), Sgt_r);                                       \
        Sg_r  += (gx);                                                         \
        float t2_ = tanh_fast(0.5f * (cx));                                    \
        St_k  += t2_;                                                          \
        St2_k  = fmaf(t2_, t2_, St2_k);                                        \
        Sgt_k  = fmaf(t2_, (dx), Sgt_k);                                       \
        Sg_k  += (dx);                                                         \
    } while (0)

        while (g + STR < HW4) {
            float4 Aa = ldcg4(prb + g);
            float4 Ga = ldcg4(rgb + g);
            float4 Ca = ldcg4(pkb + g);
            float4 Da = ldcg4(kgb + g);
            int g2 = g + STR;
            float4 Ab = ldcg4(prb + g2);
            float4 Gb = ldcg4(rgb + g2);
            float4 Cb = ldcg4(pkb + g2);
            float4 Db = ldcg4(kgb + g2);

            DICE_PROC(Aa.x, Ga.x, Ca.x, Da.x);
            DICE_PROC(Aa.y, Ga.y, Ca.y, Da.y);
            DICE_PROC(Aa.z, Ga.z, Ca.z, Da.z);
            DICE_PROC(Aa.w, Ga.w, Ca.w, Da.w);
            DICE_PROC(Ab.x, Gb.x, Cb.x, Db.x);
            DICE_PROC(Ab.y, Gb.y, Cb.y, Db.y);
            DICE_PROC(Ab.z, Gb.z, Cb.z, Db.z);
            DICE_PROC(Ab.w, Gb.w, Cb.w, Db.w);
            g += 2 * STR;
        }
        if (g < HW4) {
            float4 A = ldcg4(prb + g);
            float4 G = ldcg4(rgb + g);
            float4 C = ldcg4(pkb + g);
            float4 D = ldcg4(kgb + g);
            DICE_PROC(A.x, G.x, C.x, D.x);
            DICE_PROC(A.y, G.y, C.y, D.y);
            DICE_PROC(A.z, G.z, C.z, D.z);
            DICE_PROC(A.w, G.w, C.w, D.w);
        }
#undef DICE_PROC

        #pragma unroll
        for (int o = 16; o; o >>= 1) {
            St_r  += __shfl_down_sync(0xffffffffu, St_r,  o);
            St2_r += __shfl_down_sync(0xffffffffu, St2_r, o);
            Sgt_r += __shfl_down_sync(0xffffffffu, Sgt_r, o);
            Sg_r  += __shfl_down_sync(0xffffffffu, Sg_r,  o);
            St_k  += __shfl_down_sync(0xffffffffu, St_k,  o);
            St2_k += __shfl_down_sync(0xffffffffu, St2_k, o);
            Sgt_k += __shfl_down_sync(0xffffffffu, Sgt_k, o);
            Sg_k  += __shfl_down_sync(0xffffffffu, Sg_k,  o);
        }
        if ((tid & 31) == 0) {
            atomicAdd(&g_dice[b*8+0], St_r);  atomicAdd(&g_dice[b*8+1], St2_r);
            atomicAdd(&g_dice[b*8+2], Sgt_r); atomicAdd(&g_dice[b*8+3], Sg_r);
            atomicAdd(&g_dice[b*8+4], St_k);  atomicAdd(&g_dice[b*8+5], St2_k);
            atomicAdd(&g_dice[b*8+6], Sgt_k); atomicAdd(&g_dice[b*8+7], Sg_k);
        }
    }

    __threadfence();
    __syncthreads();
    if (tid == 0)
        s_last = (atomicAdd(&g_sem, 1u) == (unsigned)(NBLK - 1)) ? 1u : 0u;
    __syncthreads();
    if (!s_last) return;

    // ---------------- finalize (last block only) ----------------
    __threadfence();

    float lr = 0.f, lk = 0.f, lagg = 0.f, ldis = 0.f;
    if (tid < NB) {
        float T2[NSEG], ct[NSEG], K2[NSEG], ck[NSEG], Ssd[NSEG], a[8];
        #pragma unroll
        for (int i = 0; i < NSEG; i++) {
            T2[i]  = g_hist[tid * NACC + i];
            ct[i]  = g_hist[tid * NACC + 9 + i];
            K2[i]  = g_hist[tid * NACC + 18 + i];
            ck[i]  = g_hist[tid * NACC + 27 + i];
            Ssd[i] = g_hist[tid * NACC + 36 + i];
        }

        float St  = g_dice[tid*8+0], St2 = g_dice[tid*8+1];
        float Sgt = g_dice[tid*8+2], Sg  = g_dice[tid*8+3];
        float I = 0.5f * (Sgt + Sg);
        float P = 0.25f * (NPXF + 2.f * St + St2);
        lr = 1.0f - (2.0f * I + EPSF) / ((P + EPSF) + (Sg + EPSF));

        St  = g_dice[tid*8+4]; St2 = g_dice[tid*8+5];
        Sgt = g_dice[tid*8+6]; Sg  = g_dice[tid*8+7];
        I = 0.5f * (Sgt + Sg);
        P = 0.25f * (NPXF + 2.f * St + St2);
        lk = 1.0f - (2.0f * I + EPSF) / ((P + EPSF) + (Sg + EPSF));

        #pragma unroll 1
        for (int i = 1; i < NSEG; i++) {
            float inv = 1.0f / (ck[i] + 1.0f);
            float n2  = T2[i] - (2.0f * inv - inv * inv) * Ssd[i]
                        + inv * inv * (K2[i] - Ssd[i]);
            float nrm = sqrtf(fmaxf(n2, 0.0f));
            float d   = nrm - 0.5f;                    // SIGMA_AGG (no clamp)
            lagg += logf(d * d + 1.0f) / (ct[i] + 1.0f);
            float c1 = ck[i] + 0.001f;
            a[i - 1] = K2[i] / (c1 * c1);
        }
        #pragma unroll 1
        for (int i = 0; i < 8; i++)
            #pragma unroll 1
            for (int j = i + 1; j < 8; j++) {
                float pr_ = 3.0f - sqrtf(a[i] + a[j]); // SIGMA_DIS
                ldis += logf(pr_ * pr_ + 1.0f);
            }
        ldis *= (1.0f / 56.0f);
    }

    if (tid < 32) {
        #pragma unroll
        for (int o = 16; o; o >>= 1) {
            lr   += __shfl_down_sync(0xffffffffu, lr,   o);
            lk   += __shfl_down_sync(0xffffffffu, lk,   o);
            lagg += __shfl_down_sync(0xffffffffu, lagg, o);
            ldis += __shfl_down_sync(0xffffffffu, ldis, o);
        }
        if (tid == 0) {
            out[0] = lr + 0.5f * lk + 0.25f * (lagg + ldis);  // ALPHA, BETA
            out[1] = lr;
            out[2] = lk;
            out[3] = lagg;
            out[4] = ldis;
        }
    }
    __syncthreads();

    // reset scratch for next graph replay
    for (int i = tid; i < NB * NACC; i += NTH) g_hist[i] = 0.f;
    for (int i = tid; i < NB * 8;    i += NTH) g_dice[i] = 0.f;
    __threadfence();
    __syncthreads();
    if (tid == 0) g_sem = 0u;
}

extern "C" void kernel_launch(void* const* d_in, const int* in_sizes, int n_in,
                              void* d_out, int out_size) {
    (void)in_sizes; (void)n_in; (void)out_size;
    dim3 grid(BPBS + BPBD, NB);
    pan_fused<<<grid, NTH>>>(
        (const float4*)d_in[0], (const float4*)d_in[1],
        (const float4*)d_in[2], (const float4*)d_in[3],
        (const float4*)d_in[4],
        (const int4*)d_in[5],  (const int4*)d_in[6],
        (float*)d_out);
}